// round 4
// baseline (speedup 1.0000x reference)
#include <cuda_runtime.h>
#include <math.h>

#define R 32
#define V 50257
#define VR (V * R)            // 1,608,224 floats per i-slab
#define BATCH 1024
#define NSTEP 8
#define EPS 1e-10f

#define THREADS 256
#define GATHER_BLOCKS 128     // 128 blocks * 8 warps = 1024 warps = 1 / batch row
#define RED_BX 24             // reduction blocks per i
#define RED_BLOCKS (RED_BX * R)            // 768
#define NBLOCKS (GATHER_BLOCKS + RED_BLOCKS)  // 896 <= 152 SMs * 6 = one wave

// Scratch (no allocation allowed anywhere)
__device__ float g_Mpart[RED_BLOCKS * R];   // per-block partial sums of M
__device__ float g_pt[BATCH];               // prob_tilde per row
__device__ unsigned int g_count = 0;        // completion counter (reset each call)

__global__ __launch_bounds__(THREADS, 6)
void tjd_fused_kernel(const float* __restrict__ alpha,
                      const float* __restrict__ beta,
                      const float* __restrict__ core,
                      const int*   __restrict__ ids,
                      float* __restrict__ out, int out_size)
{
    const int bid = blockIdx.x;
    const int tid = threadIdx.x;

    __shared__ float sred[R];        // reduction-path block reduce
    __shared__ float sM[R * R];      // finalize: M matrix
    __shared__ float sloss[THREADS]; // finalize: loss reduce
    __shared__ float s_z;
    __shared__ int   s_last;

    if (bid < GATHER_BLOCKS) {
        // ---------------- gather/chain: one warp per batch row ----------------
        const int row  = bid * (THREADS / 32) + (tid >> 5);
        const int lane = tid & 31;
        const int* myids = ids + row * NSTEP;

        float v = fmaxf(alpha[lane], 0.0f) + EPS;   // lane holds v[lane]

        #pragma unroll 1
        for (int t = 0; t < NSTEP; t++) {
            const float* base = core + (size_t)myids[t] * R + lane;
            float nv = 0.0f;
            // two half-batches of 16 keeps regs under the launch-bounds cap
            #pragma unroll 1
            for (int h = 0; h < 2; h++) {
                float g[16];
                #pragma unroll
                for (int i = 0; i < 16; i++)
                    g[i] = __ldg(base + (size_t)(h * 16 + i) * VR);
                #pragma unroll
                for (int i = 0; i < 16; i++)
                    nv = fmaf(__shfl_sync(0xffffffffu, v, h * 16 + i),
                              fmaxf(g[i], 0.0f) + EPS, nv);
            }
            v = nv;
        }

        float pt = v * (fmaxf(beta[lane], 0.0f) + EPS);
        #pragma unroll
        for (int o = 16; o; o >>= 1)
            pt += __shfl_xor_sync(0xffffffffu, pt, o);
        if (lane == 0) g_pt[row] = pt;
    } else {
        // ------------- reduction: M[i][j] = sum_v relu(core[i,v,j]) -----------
        const int rb = bid - GATHER_BLOCKS;
        const int i  = rb / RED_BX;
        const int bx = rb % RED_BX;

        const float4* p = (const float4*)(core + (size_t)i * VR);
        const int n4 = VR / 4;                   // 402,056 — exact, no tail

        // stride (RED_BX*THREADS) % 8 == 0, so each thread's 4 j-lanes are
        // fixed: jb = (tid & 7) * 4
        float a0 = 0.f, a1 = 0.f, a2 = 0.f, a3 = 0.f;
        #pragma unroll 4
        for (int idx = bx * THREADS + tid; idx < n4; idx += RED_BX * THREADS) {
            float4 g = __ldg(p + idx);
            a0 += fmaxf(g.x, 0.0f);
            a1 += fmaxf(g.y, 0.0f);
            a2 += fmaxf(g.z, 0.0f);
            a3 += fmaxf(g.w, 0.0f);
        }

        if (tid < R) sred[tid] = 0.0f;
        __syncthreads();
        const int jb = (tid & 7) * 4;
        atomicAdd(&sred[jb + 0], a0);
        atomicAdd(&sred[jb + 1], a1);
        atomicAdd(&sred[jb + 2], a2);
        atomicAdd(&sred[jb + 3], a3);
        __syncthreads();
        if (tid < R)
            g_Mpart[rb * R + tid] = sred[tid];
    }

    // ------------------- last-block-done finalize -------------------
    __syncthreads();                       // all block stores issued
    if (tid == 0) {
        __threadfence();                   // make partials/g_pt visible
        s_last = (atomicAdd(&g_count, 1u) == (unsigned)(NBLOCKS - 1));
    }
    __syncthreads();
    if (!s_last) return;

    // sum the 24 partials per M entry, fold the per-element eps back in
    for (int e = tid; e < R * R; e += THREADS) {
        const int i = e >> 5, j = e & 31;
        float s = 0.0f;
        #pragma unroll
        for (int b = 0; b < RED_BX; b++)
            s += g_Mpart[(i * RED_BX + b) * R + j];
        sM[e] = s + (float)V * EPS;
    }
    __syncthreads();

    // z = a (M)^8 b  (warp 0; overflows to +inf ~step 7 exactly like fp32 ref)
    if (tid < R) {
        float u = fmaxf(alpha[tid], 0.0f) + EPS;
        #pragma unroll 1
        for (int s = 0; s < NSTEP; s++) {
            float nu = 0.0f;
            #pragma unroll
            for (int i = 0; i < R; i++)
                nu = fmaf(__shfl_sync(0xffffffffu, u, i), sM[i * R + tid], nu);
            u = nu;
        }
        float z = u * (fmaxf(beta[tid], 0.0f) + EPS);
        #pragma unroll
        for (int o = 16; o; o >>= 1)
            z += __shfl_xor_sync(0xffffffffu, z, o);
        if (tid == 0) s_z = z;
    }
    __syncthreads();

    const float z = s_z;
    float lacc = 0.0f;
    for (int row = tid; row < BATCH; row += THREADS) {
        const float prob = g_pt[row] / z;           // finite/inf -> 0 like ref
        if (out_size >= BATCH + 1)  out[1 + row] = prob;   // [loss, prob...]
        else if (out_size == BATCH) out[row]     = prob;   // prob only
        lacc -= logf(prob + EPS);
    }
    sloss[tid] = lacc;
    __syncthreads();
    #pragma unroll
    for (int s = THREADS / 2; s > 0; s >>= 1) {
        if (tid < s) sloss[tid] += sloss[tid + s];
        __syncthreads();
    }
    if (tid == 0) {
        if (out_size != BATCH) out[0] = sloss[0] / (float)BATCH;
        g_count = 0;                        // reset for next graph replay
    }
}

// ---------------------------------------------------------------------------
extern "C" void kernel_launch(void* const* d_in, const int* in_sizes, int n_in,
                              void* d_out, int out_size) {
    const float* alpha = (const float*)d_in[0];   // (32,)
    const float* beta  = (const float*)d_in[1];   // (32,)
    const float* core  = (const float*)d_in[2];   // (32, 50257, 32)
    const int*   ids   = (const int*)  d_in[3];   // (1024, 8)

    tjd_fused_kernel<<<NBLOCKS, THREADS>>>(alpha, beta, core, ids,
                                           (float*)d_out, out_size);
}

// round 5
// speedup vs baseline: 1.1134x; 1.1134x over previous
#include <cuda_runtime.h>
#include <math.h>

#define R 32
#define V 50257
#define VR (V * R)            // 1,608,224 floats per i-slab
#define BATCH 1024
#define NSTEP 8
#define EPS 1e-10f

#define THREADS 256
#define GATHER_BLOCKS 128     // 128 blocks * 8 warps = 1024 warps = 1 / batch row
#define RED_BX 40             // reduction blocks per i
#define RED_BLOCKS (RED_BX * R)               // 1280
#define NBLOCKS (GATHER_BLOCKS + RED_BLOCKS)  // 1408

// Scratch (no allocation allowed anywhere)
__device__ float g_Mpart[RED_BLOCKS * R];   // per-block partial sums of M
__device__ float g_pt[BATCH];               // prob_tilde per row
__device__ unsigned int g_count = 0;        // completion counter

__global__ __launch_bounds__(THREADS)
void tjd_fused_kernel(const float* __restrict__ alpha,
                      const float* __restrict__ beta,
                      const float* __restrict__ core,
                      const int*   __restrict__ ids,
                      float* __restrict__ out, int out_size)
{
    const int bid = blockIdx.x;
    const int tid = threadIdx.x;

    __shared__ float sred[R];        // reduction-path block reduce
    __shared__ float sM[R * R];      // finalize: M matrix
    __shared__ float sloss[THREADS]; // finalize: loss reduce
    __shared__ float s_z;
    __shared__ int   s_last;

    if (bid < GATHER_BLOCKS) {
        // ---------------- gather/chain: one warp per batch row ----------------
        const int row  = bid * (THREADS / 32) + (tid >> 5);
        const int lane = tid & 31;
        const int* myids = ids + row * NSTEP;

        float v = fmaxf(alpha[lane], 0.0f) + EPS;   // lane holds v[lane]

        #pragma unroll 1
        for (int t = 0; t < NSTEP; t++) {
            const float* base = core + (size_t)myids[t] * R + lane;
            // 32 independent loads (full-MLP; 128B coalesced per i across warp)
            float g[R];
            #pragma unroll
            for (int i = 0; i < R; i++)
                g[i] = __ldg(base + (size_t)i * VR);
            float nv = 0.0f;
            #pragma unroll
            for (int i = 0; i < R; i++)
                nv = fmaf(__shfl_sync(0xffffffffu, v, i),
                          fmaxf(g[i], 0.0f) + EPS, nv);
            v = nv;
        }

        float pt = v * (fmaxf(beta[lane], 0.0f) + EPS);
        #pragma unroll
        for (int o = 16; o; o >>= 1)
            pt += __shfl_xor_sync(0xffffffffu, pt, o);
        if (lane == 0) g_pt[row] = pt;
    } else {
        // ------------- reduction: M[i][j] = sum_v relu(core[i,v,j]) -----------
        const int rb = bid - GATHER_BLOCKS;
        const int i  = rb / RED_BX;
        const int bx = rb % RED_BX;

        const float4* p = (const float4*)(core + (size_t)i * VR);
        const int n4     = VR / 4;               // 402,056
        const int stride = RED_BX * THREADS;     // 10,240 (mult of 8 -> fixed j)

        // two accumulator chains per j component to shorten FADD dependency
        float x0=0.f, y0=0.f, z0=0.f, w0=0.f;
        float x1=0.f, y1=0.f, z1=0.f, w1=0.f;

        int idx = bx * THREADS + tid;
        // main loop: 8 outstanding float4 loads (streaming, evict-first)
        for (; idx + 7 * stride < n4; idx += 8 * stride) {
            float4 g0 = __ldcs(p + idx + 0 * stride);
            float4 g1 = __ldcs(p + idx + 1 * stride);
            float4 g2 = __ldcs(p + idx + 2 * stride);
            float4 g3 = __ldcs(p + idx + 3 * stride);
            float4 g4 = __ldcs(p + idx + 4 * stride);
            float4 g5 = __ldcs(p + idx + 5 * stride);
            float4 g6 = __ldcs(p + idx + 6 * stride);
            float4 g7 = __ldcs(p + idx + 7 * stride);
            x0 += fmaxf(g0.x,0.f); y0 += fmaxf(g0.y,0.f); z0 += fmaxf(g0.z,0.f); w0 += fmaxf(g0.w,0.f);
            x1 += fmaxf(g1.x,0.f); y1 += fmaxf(g1.y,0.f); z1 += fmaxf(g1.z,0.f); w1 += fmaxf(g1.w,0.f);
            x0 += fmaxf(g2.x,0.f); y0 += fmaxf(g2.y,0.f); z0 += fmaxf(g2.z,0.f); w0 += fmaxf(g2.w,0.f);
            x1 += fmaxf(g3.x,0.f); y1 += fmaxf(g3.y,0.f); z1 += fmaxf(g3.z,0.f); w1 += fmaxf(g3.w,0.f);
            x0 += fmaxf(g4.x,0.f); y0 += fmaxf(g4.y,0.f); z0 += fmaxf(g4.z,0.f); w0 += fmaxf(g4.w,0.f);
            x1 += fmaxf(g5.x,0.f); y1 += fmaxf(g5.y,0.f); z1 += fmaxf(g5.z,0.f); w1 += fmaxf(g5.w,0.f);
            x0 += fmaxf(g6.x,0.f); y0 += fmaxf(g6.y,0.f); z0 += fmaxf(g6.z,0.f); w0 += fmaxf(g6.w,0.f);
            x1 += fmaxf(g7.x,0.f); y1 += fmaxf(g7.y,0.f); z1 += fmaxf(g7.z,0.f); w1 += fmaxf(g7.w,0.f);
        }
        // tail
        for (; idx < n4; idx += stride) {
            float4 g = __ldcs(p + idx);
            x0 += fmaxf(g.x,0.f); y0 += fmaxf(g.y,0.f);
            z0 += fmaxf(g.z,0.f); w0 += fmaxf(g.w,0.f);
        }
        const float ax = x0 + x1, ay = y0 + y1, az = z0 + z1, aw = w0 + w1;

        if (tid < R) sred[tid] = 0.0f;
        __syncthreads();
        const int jb = (tid & 7) * 4;
        atomicAdd(&sred[jb + 0], ax);
        atomicAdd(&sred[jb + 1], ay);
        atomicAdd(&sred[jb + 2], az);
        atomicAdd(&sred[jb + 3], aw);
        __syncthreads();
        if (tid < R)
            g_Mpart[rb * R + tid] = sred[tid];
    }

    // ------------------- last-block-done finalize -------------------
    __syncthreads();
    if (tid == 0) {
        __threadfence();                   // make partials/g_pt visible
        s_last = (atomicAdd(&g_count, 1u) == (unsigned)(NBLOCKS - 1));
    }
    __syncthreads();
    if (!s_last) return;

    // sum the RED_BX partials per M entry; fold per-element eps back in
    for (int e = tid; e < R * R; e += THREADS) {
        const int i = e >> 5, j = e & 31;
        float s = 0.0f;
        #pragma unroll 8
        for (int b = 0; b < RED_BX; b++)
            s += g_Mpart[(i * RED_BX + b) * R + j];
        sM[e] = s + (float)V * EPS;
    }
    __syncthreads();

    // z = a (M)^8 b  (warp 0; overflows to +inf ~step 7 exactly like fp32 ref)
    if (tid < R) {
        float u = fmaxf(alpha[tid], 0.0f) + EPS;
        #pragma unroll 1
        for (int s = 0; s < NSTEP; s++) {
            float nu = 0.0f;
            #pragma unroll
            for (int i = 0; i < R; i++)
                nu = fmaf(__shfl_sync(0xffffffffu, u, i), sM[i * R + tid], nu);
            u = nu;
        }
        float z = u * (fmaxf(beta[tid], 0.0f) + EPS);
        #pragma unroll
        for (int o = 16; o; o >>= 1)
            z += __shfl_xor_sync(0xffffffffu, z, o);
        if (tid == 0) s_z = z;
    }
    __syncthreads();

    const float z = s_z;
    float lacc = 0.0f;
    for (int row = tid; row < BATCH; row += THREADS) {
        const float prob = g_pt[row] / z;           // finite/inf -> 0 like ref
        if (out_size >= BATCH + 1)  out[1 + row] = prob;   // [loss, prob...]
        else if (out_size == BATCH) out[row]     = prob;   // prob only
        lacc -= logf(prob + EPS);
    }
    sloss[tid] = lacc;
    __syncthreads();
    #pragma unroll
    for (int s = THREADS / 2; s > 0; s >>= 1) {
        if (tid < s) sloss[tid] += sloss[tid + s];
        __syncthreads();
    }
    if (tid == 0) {
        if (out_size != BATCH) out[0] = sloss[0] / (float)BATCH;
        g_count = 0;                        // reset for next graph replay
    }
}

// ---------------------------------------------------------------------------
extern "C" void kernel_launch(void* const* d_in, const int* in_sizes, int n_in,
                              void* d_out, int out_size) {
    const float* alpha = (const float*)d_in[0];   // (32,)
    const float* beta  = (const float*)d_in[1];   // (32,)
    const float* core  = (const float*)d_in[2];   // (32, 50257, 32)
    const int*   ids   = (const int*)  d_in[3];   // (1024, 8)

    tjd_fused_kernel<<<NBLOCKS, THREADS>>>(alpha, beta, core, ids,
                                           (float*)d_out, out_size);
}